// round 17
// baseline (speedup 1.0000x reference)
#include <cuda_runtime.h>
#include <cuda_fp16.h>
#include <cstdint>

typedef unsigned long long ull;

#define GI   1220
#define GHW  1232      // padded fp16 g row (16B-aligned)
#define HID  150
#define NMAX 50000
#define PMAX 100000
#define CPAD 160
#define ABS  320
#define NCH2 39        // K chunks of 32
#define RS2  80        // smem row stride (bytes) for fp16 chunk-32 tiles -> conflict-free LDSM
#define H1S  336       // h1 fp16 row stride bytes (84r mod 32 distinct -> conflict-free)

// ===================== device scratch (no allocations allowed) =====================
__device__ float  d_AB[(size_t)NMAX * ABS];      // 64 MB: per-mention  g@[W1a|W1b]
__device__ __half d_gh[(size_t)NMAX * GHW];      // 123 MB: fp16 image of g (zero-padded cols)
__device__ uint4  d_WcTh[NCH2 * 10240 / 16];     // W1c^T fp16 tiles [160 x 32] per chunk
__device__ uint4  d_WabTh[NCH2 * 20480 / 16];    // [W1a|W1b]^T fp16 tiles [320 x 32] per chunk
__device__ uint4  d_W2Th[5 * 10240 / 16];        // W2^T fp16 tiles [160 x 32] per k-chunk
__device__ float  d_Dt[9 * CPAD];                // dist table (+b1)
__device__ float  d_Gt[8 * CPAD];
__device__ float  d_St[3 * CPAD];

// ===================== helpers =====================
__device__ __forceinline__ uint32_t smem_to_u32(const void* p) {
    uint32_t a;
    asm("{ .reg .u64 t; cvta.to.shared.u64 t, %1; cvt.u32.u64 %0, t; }" : "=r"(a) : "l"(p));
    return a;
}

__device__ __forceinline__ void mma16816(float c[4],
                                         uint32_t a0, uint32_t a1, uint32_t a2, uint32_t a3,
                                         uint32_t b0, uint32_t b1) {
    asm volatile(
        "mma.sync.aligned.m16n8k16.row.col.f32.f16.f16.f32 "
        "{%0,%1,%2,%3}, {%4,%5,%6,%7}, {%8,%9}, {%0,%1,%2,%3};"
        : "+f"(c[0]), "+f"(c[1]), "+f"(c[2]), "+f"(c[3])
        : "r"(a0), "r"(a1), "r"(a2), "r"(a3), "r"(b0), "r"(b1));
}

__device__ __forceinline__ void ldsm4(uint32_t r[4], uint32_t addr) {
    asm volatile("ldmatrix.sync.aligned.m8n8.x4.shared.b16 {%0,%1,%2,%3}, [%4];"
        : "=r"(r[0]), "=r"(r[1]), "=r"(r[2]), "=r"(r[3]) : "r"(addr));
}

__device__ __forceinline__ void cp16(uint32_t dst, const void* src) {
    asm volatile("cp.async.cg.shared.global [%0], [%1], 16;" :: "r"(dst), "l"(src));
}
#define CP_COMMIT() asm volatile("cp.async.commit_group;" ::: "memory")
#define CP_WAIT0()  asm volatile("cp.async.wait_group 0;" ::: "memory")

union HPack { __half v[4]; ull u; };
__device__ __forceinline__ ull cvt4h(float4 x) {
    HPack H;
    H.v[0] = __float2half_rn(x.x);
    H.v[1] = __float2half_rn(x.y);
    H.v[2] = __float2half_rn(x.z);
    H.v[3] = __float2half_rn(x.w);
    return H.u;
}

// wide MMA inner step: 32x80 warp tile, 2 m-frags x 10 n-frags, single fp16 pass.
// A from (Abase, astr bytes, akoff bytes); B chunk-32, stride RS2.  s in {0,1}.
__device__ __forceinline__ void mma_chunk10(float (*acc)[10][4],
        uint32_t Abase, uint32_t Bh, int s, int rowbase, int colbase, int lane,
        int astr, int akoff) {
    int kb2 = s * 32;
    int l7 = lane & 7, g = lane >> 3;
    uint32_t aoff = (uint32_t)((rowbase + (g & 1) * 8 + l7) * astr + akoff + kb2 + (g >> 1) * 16);
    uint32_t ah[2][4];
    ldsm4(ah[0], Abase + aoff);
    ldsm4(ah[1], Abase + aoff + 16 * astr);
    uint32_t boff = (uint32_t)((colbase + (g >> 1) * 8 + l7) * RS2 + kb2 + (g & 1) * 16);
    #pragma unroll
    for (int fp = 0; fp < 5; ++fp) {
        uint32_t bh[4];
        ldsm4(bh, Bh + boff + fp * 16 * RS2);
        #pragma unroll
        for (int half = 0; half < 2; ++half) {
            int f = fp * 2 + half;
            uint32_t b0h = bh[half * 2], b1h = bh[half * 2 + 1];
            #pragma unroll
            for (int mi = 0; mi < 2; ++mi)
                mma16816(acc[mi][f], ah[mi][0], ah[mi][1], ah[mi][2], ah[mi][3], b0h, b1h);
        }
    }
}

// ===================== weight prep =====================

__global__ void prep_wtiles(const float* __restrict__ W1) {
    int q = blockIdx.x;   // K-chunk of 32
    int t = threadIdx.x;
    __half* ch = (__half*)d_WcTh;
    for (int idx = t; idx < 160 * 32; idx += 256) {
        int n = idx >> 5, kk = idx & 31, k = q * 32 + kk;
        float v = (k < GI && n < HID) ? W1[(2 * GI + k) * HID + n] : 0.f;
        ch[(size_t)q * 5120 + (size_t)n * 32 + kk] = __float2half_rn(v);
    }
    __half* ah = (__half*)d_WabTh;
    for (int idx = t; idx < 320 * 32; idx += 256) {
        int n = idx >> 5, kk = idx & 31, k = q * 32 + kk;
        float v = 0.f;
        if (k < GI) {
            if (n < HID)                        v = W1[k * HID + n];
            else if (n >= 160 && n < 160 + HID) v = W1[(GI + k) * HID + (n - 160)];
        }
        ah[(size_t)q * 10240 + (size_t)n * 32 + kk] = __float2half_rn(v);
    }
}

__global__ void prep_w2(const float* __restrict__ W2) {
    int q = blockIdx.x;   // 0..4
    int t = threadIdx.x;
    __half* wh = (__half*)d_W2Th;
    for (int idx = t; idx < 160 * 32; idx += 256) {
        int n = idx >> 5, kk = idx & 31, k = q * 32 + kk;
        float v = (k < HID && n < HID) ? W2[k * HID + n] : 0.f;
        wh[(size_t)q * 5120 + (size_t)n * 32 + kk] = __float2half_rn(v);
    }
}

__global__ void prep_tabs(const float* __restrict__ de, const float* __restrict__ ge,
                          const float* __restrict__ se, const float* __restrict__ W1,
                          const float* __restrict__ b1) {
    int c = threadIdx.x;     // 0..159
    for (int d = 0; d < 9; ++d) {
        float v = 0.f;
        if (c < HID) {
            v = b1[c];
            for (int t = 0; t < 20; ++t) v += de[d*20 + t] * W1[(3*GI + t) * HID + c];
        }
        d_Dt[d * CPAD + c] = v;
    }
    for (int g = 0; g < 8; ++g) {
        float v = 0.f;
        if (c < HID)
            for (int t = 0; t < 20; ++t) v += ge[g*20 + t] * W1[(3*GI + 20 + t) * HID + c];
        d_Gt[g * CPAD + c] = v;
    }
    for (int s = 0; s < 3; ++s) {
        float v = 0.f;
        if (c < HID)
            for (int t = 0; t < 20; ++t) v += se[s*20 + t] * W1[(3*GI + 40 + t) * HID + c];
        d_St[s * CPAD + c] = v;
    }
}

// ===================== T1: AB = g @ [W1a|W1b], 128 rows x 320 cols / CTA, 512 thr =====================
// smem: A bufs @0 (2 x 10240) -> 20480, B bufs @20480 (2 x 25600) -> 71680
#define T1_B    20480
#define T1_SMEM 71680

__device__ __forceinline__ void cpB_T1(uint32_t bh, int q, int t) {
    const uint4* sH = d_WabTh + (size_t)q * 1280;
    #pragma unroll
    for (int i = 0; i < 3; ++i) {
        int idx = t + 512 * i;              // 0..1279
        if (idx < 1280) {
            int n = idx >> 2, seg = idx & 3;
            cp16(bh + n * RS2 + seg * 16, sH + idx);
        }
    }
}

__device__ __forceinline__ void ldgRow2(const float4* grow, int kb0, float4 x[2]) {
    #pragma unroll
    for (int u = 0; u < 2; ++u) {
        int kb = kb0 + 4 * u;
        x[u] = (kb < GI) ? grow[kb >> 2] : make_float4(0.f, 0.f, 0.f, 0.f);
    }
}
__device__ __forceinline__ void stsRow2(unsigned char* Ah, int r, int koff, const float4 x[2],
                                        __half* ghrow, int kb0) {
    ull h0 = cvt4h(x[0]);
    ull h1v = cvt4h(x[1]);
    uint32_t off = (uint32_t)(r * RS2 + koff * 2);
    *(ull*)(Ah + off)     = h0;
    *(ull*)(Ah + off + 8) = h1v;
    if (kb0 + 8 <= GHW) {
        uint4 v;
        v.x = (uint32_t)h0;  v.y = (uint32_t)(h0 >> 32);
        v.z = (uint32_t)h1v; v.w = (uint32_t)(h1v >> 32);
        *(uint4*)(ghrow + kb0) = v;
    }
}

__global__ __launch_bounds__(512, 1) void gemm_ab_pipe(const float* __restrict__ g, int N) {
    extern __shared__ unsigned char sm[];
    uint32_t sb = smem_to_u32(sm);
    int t = threadIdx.x, wid = t >> 5, lane = t & 31;
    int g4 = lane >> 2, tq = lane & 3;
    int wr = wid >> 2, wc = wid & 3;              // 4 x 4 warp grid (32 x 80 tiles)
    int rowbase = wr * 32, colbase = wc * 80;
    int n0 = blockIdx.x * 128;
    int r = t >> 2, q4 = t & 3, kth = 8 * q4;     // A staging: 128 rows, 8 floats/thread
    int row = n0 + r; if (row >= N) row = N - 1;
    const float4* grow = (const float4*)(g + (size_t)row * GI);
    __half* ghrow = d_gh + (size_t)row * GHW;

    float acc[2][10][4];
    #pragma unroll
    for (int mi = 0; mi < 2; ++mi)
        #pragma unroll
        for (int f = 0; f < 10; ++f)
            #pragma unroll
            for (int e = 0; e < 4; ++e) acc[mi][f][e] = 0.f;

    // prologue: stage chunk 0
    {
        float4 x[2];
        ldgRow2(grow, kth, x);
        stsRow2(sm, r, kth, x, ghrow, kth);
        cpB_T1(sb + T1_B, 0, t);
        CP_COMMIT(); CP_WAIT0();
    }
    __syncthreads();

    for (int q = 0; q < NCH2; ++q) {
        int cb = q & 1, nb = cb ^ 1;
        uint32_t Ah = sb + cb * 10240;
        uint32_t Bh = sb + T1_B + cb * 25600;
        unsigned char* nAh = sm + nb * 10240;
        bool more = (q + 1 < NCH2);
        if (more) { cpB_T1(sb + T1_B + nb * 25600, q + 1, t); CP_COMMIT(); }
        float4 x0[2];
        int kn = (q + 1) * 32 + kth;
        if (more) ldgRow2(grow, kn, x0);
        mma_chunk10(acc, Ah, Bh, 0, rowbase, colbase, lane, RS2, 0);
        mma_chunk10(acc, Ah, Bh, 1, rowbase, colbase, lane, RS2, 0);
        if (more) { stsRow2(nAh, r, kth, x0, ghrow, kn); CP_WAIT0(); }
        __syncthreads();
    }

    #pragma unroll
    for (int mi = 0; mi < 2; ++mi) {
        #pragma unroll
        for (int f = 0; f < 10; ++f) {
            int rr = rowbase + mi * 16 + g4;
            int col = colbase + f * 8 + 2 * tq;
            int n = n0 + rr;
            if (n < N)
                *(float2*)(d_AB + (size_t)n * ABS + col) = make_float2(acc[mi][f][0], acc[mi][f][1]);
            n = n0 + rr + 8;
            if (n < N)
                *(float2*)(d_AB + (size_t)n * ABS + col) = make_float2(acc[mi][f][2], acc[mi][f][3]);
        }
    }
}

// ===================== T2 fused (256 pairs/CTA, 512 thr): bilinear MMA + reg epilogue + layer2 MMA =====================
// smem map:
//  0..5120      indices m/a/d/g/s (5 x 1024B)
//  5120..5760   w3s (160 f)    5760..6400  b2s (160 f)
//  6400..47360  A bufs (2 x 20480)   [main loop]
//  47360..72960 B bufs (2 x 12800)   [main loop]
//  6400..92416  h1h fp16 [256 x 168h, stride 336B]   (aliases A/B after loop)
//  92416..105216 W2T buf (12800)
//  105216..107264 rowpart [2][256] f
#define F_A    6400
#define F_B    47360
#define F_H1H  6400
#define F_W2B  92416
#define F_RP   105216
#define F_SMEM 107264

__device__ __forceinline__ void cpB_tiles(uint32_t bh, const uint4* srcBase, int q, int t) {
    const uint4* sH = srcBase + (size_t)q * 640;
    #pragma unroll
    for (int i = 0; i < 2; ++i) {
        int idx = t + 512 * i;
        if (idx < 640) {
            int n = idx >> 2, seg = idx & 3;
            cp16(bh + n * RS2 + seg * 16, sH + idx);
        }
    }
}

__device__ __forceinline__ void ldgPair128(const uint4* ir, const uint4* jr, int kb0,
                                           uint4 xi[2], uint4 xj[2]) {
    #pragma unroll
    for (int u = 0; u < 2; ++u) {
        int kb = kb0 + 8 * u;
        if (kb + 8 <= GHW) { xi[u] = ir[kb >> 3]; xj[u] = jr[kb >> 3]; }
        else { xi[u] = make_uint4(0, 0, 0, 0); xj[u] = xi[u]; }
    }
}
__device__ __forceinline__ void stsPair128(unsigned char* Ah, int r, int koff,
                                           const uint4 xi[2], const uint4 xj[2]) {
    #pragma unroll
    for (int u = 0; u < 2; ++u) {
        uint4 p;
        *(__half2*)&p.x = __hmul2(*(__half2*)&xi[u].x, *(__half2*)&xj[u].x);
        *(__half2*)&p.y = __hmul2(*(__half2*)&xi[u].y, *(__half2*)&xj[u].y);
        *(__half2*)&p.z = __hmul2(*(__half2*)&xi[u].z, *(__half2*)&xj[u].z);
        *(__half2*)&p.w = __hmul2(*(__half2*)&xi[u].w, *(__half2*)&xj[u].w);
        *(uint4*)(Ah + r * RS2 + (koff + 8 * u) * 2) = p;
    }
}

__global__ __launch_bounds__(512, 1) void bilinear_fused(
    const float* __restrict__ ms,
    const float* __restrict__ b2, const float* __restrict__ W3,
    const float* __restrict__ b3,
    const int* __restrict__ mid,  const int* __restrict__ aid,
    const int* __restrict__ did,  const int* __restrict__ gid,
    const int* __restrict__ sid,
    float* __restrict__ out, int P)
{
    extern __shared__ unsigned char sm[];
    uint32_t sb = smem_to_u32(sm);
    int t = threadIdx.x, wid = t >> 5, lane = t & 31;
    int g4 = lane >> 2, tq = lane & 3;
    int wr = wid >> 1, wc = wid & 1;              // 8 x 2 warp grid (32 x 80 tiles)
    int rowbase = wr * 32, colbase = wc * 80;
    int p0 = blockIdx.x * 256;
    int* sm_m = (int*)sm;
    int* sm_a = (int*)(sm + 1024);
    int* sm_d = (int*)(sm + 2048);
    int* sm_g = (int*)(sm + 3072);
    int* sm_s = (int*)(sm + 4096);
    float* w3s = (float*)(sm + 5120);
    float* b2s = (float*)(sm + 5760);

    if (t < 256) {
        int p = p0 + t; if (p >= P) p = P - 1;
        sm_m[t] = mid[p]; sm_a[t] = aid[p]; sm_d[t] = did[p]; sm_g[t] = gid[p]; sm_s[t] = sid[p];
    }
    if (t >= 256 && t < 256 + CPAD) {
        int c = t - 256;
        w3s[c] = (c < HID) ? W3[c] : 0.f;
        b2s[c] = (c < HID) ? b2[c] : 0.f;
    }
    __syncthreads();

    int r = t >> 1, kth = 16 * (t & 1);           // A staging: 256 rows, 16 halves/thread
    const uint4* ir = (const uint4*)(d_gh + (size_t)sm_m[r] * GHW);
    const uint4* jr = (const uint4*)(d_gh + (size_t)sm_a[r] * GHW);

    float acc[2][10][4];
    #pragma unroll
    for (int mi = 0; mi < 2; ++mi)
        #pragma unroll
        for (int f = 0; f < 10; ++f)
            #pragma unroll
            for (int e = 0; e < 4; ++e) acc[mi][f][e] = 0.f;

    // prologue: stage chunk 0
    {
        uint4 xi[2], xj[2];
        ldgPair128(ir, jr, kth, xi, xj);
        stsPair128(sm + F_A, r, kth, xi, xj);
        cpB_tiles(sb + F_B, d_WcTh, 0, t);
        CP_COMMIT(); CP_WAIT0();
    }
    __syncthreads();

    for (int q = 0; q < NCH2; ++q) {
        int cb = q & 1, nb = cb ^ 1;
        uint32_t Ah = sb + F_A + cb * 20480;
        uint32_t Bh = sb + F_B + cb * 12800;
        unsigned char* nAh = sm + F_A + nb * 20480;
        bool more = (q + 1 < NCH2);
        if (more) { cpB_tiles(sb + F_B + nb * 12800, d_WcTh, q + 1, t); CP_COMMIT(); }
        uint4 xi[2], xj[2];
        int kn = (q + 1) * 32 + kth;
        if (more) ldgPair128(ir, jr, kn, xi, xj);
        mma_chunk10(acc, Ah, Bh, 0, rowbase, colbase, lane, RS2, 0);
        mma_chunk10(acc, Ah, Bh, 1, rowbase, colbase, lane, RS2, 0);
        if (more) { stsPair128(nAh, r, kth, xi, xj); CP_WAIT0(); }
        __syncthreads();
    }

    // ---- epilogue 1 (register-direct): h1 = relu(bil + AB[m] + AB[a]+160 + tabs) -> fp16 h1h ----
    __half* h1h = (__half*)(sm + F_H1H);          // stride 168 halves (336 B); aliases A/B bufs
    {
        const float2* AB2 = (const float2*)d_AB;
        const float2* Dt2 = (const float2*)d_Dt;
        const float2* Gt2 = (const float2*)d_Gt;
        const float2* St2 = (const float2*)d_St;
        #pragma unroll
        for (int mi = 0; mi < 2; ++mi) {
            #pragma unroll
            for (int rh = 0; rh < 2; ++rh) {
                int rr = rowbase + mi * 16 + rh * 8 + g4;
                const float2* am = AB2 + (size_t)sm_m[rr] * 160;
                const float2* bm = AB2 + (size_t)sm_a[rr] * 160 + 80;
                const float2* dp = Dt2 + sm_d[rr] * 80;
                const float2* gp = Gt2 + sm_g[rr] * 80;
                const float2* sp = St2 + sm_s[rr] * 80;
                #pragma unroll
                for (int f = 0; f < 10; ++f) {
                    int cp = colbase / 2 + f * 4 + tq;
                    float2 t1 = am[cp], t2 = bm[cp], t3 = dp[cp], t4 = gp[cp], t5 = sp[cp];
                    float hx = fmaxf(acc[mi][f][rh * 2 + 0] + t1.x + t2.x + t3.x + t4.x + t5.x, 0.f);
                    float hy = fmaxf(acc[mi][f][rh * 2 + 1] + t1.y + t2.y + t3.y + t4.y + t5.y, 0.f);
                    *(__half2*)(h1h + rr * 168 + 2 * cp) = __floats2half2_rn(hx, hy);
                }
            }
        }
    }
    __syncthreads();

    // ---- layer 2 via MMA: h2 = h1h @ W2 (5 k-chunks of 32, single-buffered W2T) ----
    float acc2[2][10][4];
    #pragma unroll
    for (int mi = 0; mi < 2; ++mi)
        #pragma unroll
        for (int f = 0; f < 10; ++f)
            #pragma unroll
            for (int e = 0; e < 4; ++e) acc2[mi][f][e] = 0.f;

    for (int q2 = 0; q2 < 5; ++q2) {
        if (q2) __syncthreads();                    // prev MMA reads of W2 buf done
        cpB_tiles(sb + F_W2B, d_W2Th, q2, t);
        CP_COMMIT(); CP_WAIT0();
        __syncthreads();                            // W2T visible
        mma_chunk10(acc2, sb + F_H1H, sb + F_W2B, 0, rowbase, colbase, lane, H1S, q2 * 64);
        mma_chunk10(acc2, sb + F_H1H, sb + F_W2B, 1, rowbase, colbase, lane, H1S, q2 * 64);
    }

    // ---- epilogue 2: out = relu(h2 + b2) . W3 + b3 + ms terms ----
    float pr[4] = {0.f, 0.f, 0.f, 0.f};
    #pragma unroll
    for (int f = 0; f < 10; ++f) {
        int c0 = colbase + f * 8 + 2 * tq;
        float w3a = w3s[c0], w3b = w3s[c0 + 1];
        float b2a = b2s[c0], b2b = b2s[c0 + 1];
        #pragma unroll
        for (int mi = 0; mi < 2; ++mi) {
            pr[mi * 2 + 0] += fmaxf(acc2[mi][f][0] + b2a, 0.f) * w3a
                            + fmaxf(acc2[mi][f][1] + b2b, 0.f) * w3b;
            pr[mi * 2 + 1] += fmaxf(acc2[mi][f][2] + b2a, 0.f) * w3a
                            + fmaxf(acc2[mi][f][3] + b2b, 0.f) * w3b;
        }
    }
    #pragma unroll
    for (int k = 0; k < 4; ++k) {
        pr[k] += __shfl_xor_sync(0xffffffffu, pr[k], 1);
        pr[k] += __shfl_xor_sync(0xffffffffu, pr[k], 2);
    }
    float* rowpart = (float*)(sm + F_RP);          // [2][256]
    if (tq == 0) {
        #pragma unroll
        for (int mi = 0; mi < 2; ++mi) {
            int rr = rowbase + mi * 16 + g4;
            rowpart[wc * 256 + rr]     = pr[mi * 2 + 0];
            rowpart[wc * 256 + rr + 8] = pr[mi * 2 + 1];
        }
    }
    __syncthreads();
    if (t < 256) {
        float v = rowpart[t] + rowpart[256 + t];
        int p = p0 + t;
        if (p < P)
            out[p] = v + b3[0] + ms[sm_m[t]] + ms[sm_a[t]];
    }
}

// ===================== launch =====================

extern "C" void kernel_launch(void* const* d_in, const int* in_sizes, int n_in,
                              void* d_out, int out_size)
{
    const float* g_i = (const float*)d_in[0];
    const float* ms  = (const float*)d_in[1];
    const float* de  = (const float*)d_in[2];
    const float* ge  = (const float*)d_in[3];
    const float* se  = (const float*)d_in[4];
    const float* W1  = (const float*)d_in[5];
    const float* b1  = (const float*)d_in[6];
    const float* W2  = (const float*)d_in[7];
    const float* b2  = (const float*)d_in[8];
    const float* W3  = (const float*)d_in[9];
    const float* b3  = (const float*)d_in[10];
    const int*   mid = (const int*)d_in[11];
    const int*   aid = (const int*)d_in[12];
    const int*   did = (const int*)d_in[13];
    const int*   gid = (const int*)d_in[14];
    const int*   sid = (const int*)d_in[15];

    int N = in_sizes[0] / GI;
    if (N > NMAX) N = NMAX;
    int P = in_sizes[11];
    if (P > PMAX) P = PMAX;
    float* out = (float*)d_out;

    prep_wtiles<<<NCH2, 256>>>(W1);
    prep_w2<<<5, 256>>>(W2);
    prep_tabs<<<1, CPAD>>>(de, ge, se, W1, b1);

    cudaFuncSetAttribute(gemm_ab_pipe, cudaFuncAttributeMaxDynamicSharedMemorySize, T1_SMEM);
    gemm_ab_pipe<<<(N + 127) / 128, 512, T1_SMEM>>>(g_i, N);

    cudaFuncSetAttribute(bilinear_fused, cudaFuncAttributeMaxDynamicSharedMemorySize, F_SMEM);
    bilinear_fused<<<(P + 255) / 256, 512, F_SMEM>>>(ms, b2, W3, b3,
                                                     mid, aid, did, gid, sid, out, P);
}